// round 10
// baseline (speedup 1.0000x reference)
#include <cuda_runtime.h>
#include <cuda_fp16.h>

#define NN 50000          // nodes
#define NE 50000          // hyperedges
#define CH 128            // channels
#define NNZV 800000       // nnz
#define NBE 196           // ceil(50000/256) blocks per scan domain
#define TOTB (2 * NBE)    // 392

// ---------------- scratch (device globals) -----------------------------------
__device__ float  g_w[NN];                        // sigmoid attention (per edge id)
__device__ __half g_xlh[(size_t)NN * CH];         // x @ lin_w^T  (fp16)
__device__ __half g_efh[(size_t)NE * CH];         // edge features (fp16, Binv-scaled)
__device__ int    g_cntE[NE];
__device__ int    g_cntN[NN];
__device__ int    g_posE[NE];                     // absolute fill cursors
__device__ int    g_posN[NN];
__device__ int    g_startE[NE + 1];
__device__ int    g_startN[NN + 1];
__device__ int    g_elist[NNZV];                  // node ids grouped by edge
__device__ int    g_nlist[NNZV];                  // edge ids grouped by node
__device__ int    g_blksum[TOTB];

// ---------------- kernel 0: zero counters ------------------------------------
__global__ void k_zero() {
    int i = blockIdx.x * blockDim.x + threadIdx.x;
    if (i < NE) g_cntE[i] = 0;
    if (i < NN) g_cntN[i] = 0;
}

// ---------------- kernel 1: xl = x @ lin_w^T (fp16 out), w = sigmoid(...) ---
__global__ void k_gemm(const float* __restrict__ x,
                       const float* __restrict__ lin_w,
                       const float* __restrict__ attn_w,
                       const float* __restrict__ attn_b) {
    extern __shared__ float sm[];
    float* s_lin = sm;                 // [k][c] stride 132
    float* s_x   = sm + 128 * 132;     // [k][r] stride 34 (transposed tile)

    const int tid = threadIdx.x;
    for (int idx = tid; idx < CH * CH; idx += 128) {
        int c = idx >> 7, k = idx & 127;
        s_lin[k * 132 + c] = lin_w[idx];          // transpose
    }

    const int cg = tid & 31;   // channels [4*cg, 4*cg+3]
    const int rg = tid >> 5;   // rows [8*rg, 8*rg+7] of the tile

    const int ntiles = (NN + 31) / 32;
    for (int tile = blockIdx.x; tile < ntiles; tile += gridDim.x) {
        const int row0 = tile * 32;
        __syncthreads();
        for (int idx = tid; idx < 32 * CH; idx += 128) {
            int r = idx >> 7, k = idx & 127;
            int gr = row0 + r;
            s_x[k * 34 + r] = (gr < NN) ? x[(size_t)gr * CH + k] : 0.f;
        }
        __syncthreads();

        unsigned long long acc[4][4];   // [row-pair][channel], f32x2 packed
#pragma unroll
        for (int p = 0; p < 4; p++)
#pragma unroll
            for (int c = 0; c < 4; c++) acc[p][c] = 0ull;

#pragma unroll 4
        for (int k = 0; k < CH; k++) {
            const float4 w4 = *(const float4*)(s_lin + k * 132 + cg * 4);
            unsigned long long bw[4];
            asm("mov.b64 %0, {%1, %1};" : "=l"(bw[0]) : "f"(w4.x));
            asm("mov.b64 %0, {%1, %1};" : "=l"(bw[1]) : "f"(w4.y));
            asm("mov.b64 %0, {%1, %1};" : "=l"(bw[2]) : "f"(w4.z));
            asm("mov.b64 %0, {%1, %1};" : "=l"(bw[3]) : "f"(w4.w));
            const unsigned long long* xp =
                (const unsigned long long*)(s_x + k * 34 + rg * 8);
#pragma unroll
            for (int p = 0; p < 4; p++) {
                unsigned long long a = xp[p];
#pragma unroll
                for (int c = 0; c < 4; c++)
                    asm("fma.rn.f32x2 %0, %1, %2, %3;"
                        : "=l"(acc[p][c]) : "l"(a), "l"(bw[c]), "l"(acc[p][c]));
            }
        }

#pragma unroll
        for (int p = 0; p < 4; p++) {
            float r0v[4], r1v[4];
#pragma unroll
            for (int c = 0; c < 4; c++)
                asm("mov.b64 {%0, %1}, %2;"
                    : "=f"(r0v[c]), "=f"(r1v[c]) : "l"(acc[p][c]));
            int r0 = row0 + rg * 8 + 2 * p;
            if (r0 < NN) {
                __half2 h0 = __floats2half2_rn(r0v[0], r0v[1]);
                __half2 h1 = __floats2half2_rn(r0v[2], r0v[3]);
                *(__half2*)(g_xlh + (size_t)r0 * CH + cg * 4)     = h0;
                *(__half2*)(g_xlh + (size_t)r0 * CH + cg * 4 + 2) = h1;
            }
            if (r0 + 1 < NN) {
                __half2 h0 = __floats2half2_rn(r1v[0], r1v[1]);
                __half2 h1 = __floats2half2_rn(r1v[2], r1v[3]);
                *(__half2*)(g_xlh + (size_t)(r0 + 1) * CH + cg * 4)     = h0;
                *(__half2*)(g_xlh + (size_t)(r0 + 1) * CH + cg * 4 + 2) = h1;
            }
        }

        if (tid < 32) {
            int gr = row0 + tid;
            if (gr < NN) {
                float z = 0.f;
#pragma unroll 4
                for (int k = 0; k < CH; k++)
                    z = fmaf(s_x[k * 34 + tid], attn_w[k], z);
                z += attn_b[0];
                g_w[gr] = 1.f / (1.f + __expf(-z));
            }
        }
    }
}

// ---------------- kernel 2: histogram (degrees), 4 nnz per thread ------------
__global__ void k_hist(const int* __restrict__ he) {
    int i = blockIdx.x * blockDim.x + threadIdx.x;   // over NNZV/4 quads
    if (i >= NNZV / 4) return;
    int4 n4 = ((const int4*)he)[i];
    int4 e4 = ((const int4*)(he + NNZV))[i];
    if ((unsigned)e4.x < NE) atomicAdd(&g_cntE[e4.x], 1);
    if ((unsigned)e4.y < NE) atomicAdd(&g_cntE[e4.y], 1);
    if ((unsigned)e4.z < NE) atomicAdd(&g_cntE[e4.z], 1);
    if ((unsigned)e4.w < NE) atomicAdd(&g_cntE[e4.w], 1);
    if ((unsigned)n4.x < NN) atomicAdd(&g_cntN[n4.x], 1);
    if ((unsigned)n4.y < NN) atomicAdd(&g_cntN[n4.y], 1);
    if ((unsigned)n4.z < NN) atomicAdd(&g_cntN[n4.z], 1);
    if ((unsigned)n4.w < NN) atomicAdd(&g_cntN[n4.w], 1);
}

// ---------------- scan phase A: per-block sums -------------------------------
__global__ void k_scanA() {
    const int bid = blockIdx.x;
    const bool isE = bid < NBE;
    const int lb   = isE ? bid : bid - NBE;
    const int base = lb * 256 + threadIdx.x;
    const int* cnt = isE ? g_cntE : g_cntN;
    const int len  = isE ? NE : NN;

    int v = (base < len) ? cnt[base] : 0;
#pragma unroll
    for (int off = 16; off > 0; off >>= 1)
        v += __shfl_down_sync(0xffffffffu, v, off);
    __shared__ int ws[8];
    if ((threadIdx.x & 31) == 0) ws[threadIdx.x >> 5] = v;
    __syncthreads();
    if (threadIdx.x == 0) {
        int s = 0;
#pragma unroll
        for (int w = 0; w < 8; w++) s += ws[w];
        g_blksum[bid] = s;
    }
}

// ---------------- scan phase C: block prefix + local scan + starts/cursors ---
__global__ void k_scanC() {
    const int bid = blockIdx.x;
    const bool isE = bid < NBE;
    const int lb   = isE ? bid : bid - NBE;
    const int base = lb * 256 + threadIdx.x;
    const int* cnt = isE ? g_cntE : g_cntN;
    int* strt = isE ? g_startE : g_startN;
    int* pos  = isE ? g_posE   : g_posN;
    const int len  = isE ? NE : NN;
    const int t = threadIdx.x;

    __shared__ int ws[8];
    __shared__ int s_off;
    int pre = (t < lb) ? g_blksum[(isE ? 0 : NBE) + t] : 0;
#pragma unroll
    for (int off = 16; off > 0; off >>= 1)
        pre += __shfl_down_sync(0xffffffffu, pre, off);
    if ((t & 31) == 0) ws[t >> 5] = pre;
    __syncthreads();
    if (t == 0) {
        int s = 0;
#pragma unroll
        for (int w = 0; w < 8; w++) s += ws[w];
        s_off = s;
    }
    __syncthreads();

    __shared__ int s[256];
    int c = (base < len) ? cnt[base] : 0;
    s[t] = c;
    __syncthreads();
#pragma unroll
    for (int off = 1; off < 256; off <<= 1) {
        int v = (t >= off) ? s[t - off] : 0;
        __syncthreads();
        s[t] += v;
        __syncthreads();
    }
    int excl = s[t] - c + s_off;
    if (base < len) { strt[base] = excl; pos[base] = excl; }
    if (base == len - 1) strt[len] = excl + c;
}

// ---------------- kernel 4: fill CSR lists, 4 nnz per thread -----------------
__global__ void k_fill(const int* __restrict__ he) {
    int i = blockIdx.x * blockDim.x + threadIdx.x;   // over NNZV/4 quads
    if (i >= NNZV / 4) return;
    int4 n4 = ((const int4*)he)[i];
    int4 e4 = ((const int4*)(he + NNZV))[i];
#pragma unroll
    for (int q = 0; q < 4; q++) {
        int n = (q == 0) ? n4.x : (q == 1) ? n4.y : (q == 2) ? n4.z : n4.w;
        int e = (q == 0) ? e4.x : (q == 1) ? e4.y : (q == 2) ? e4.z : e4.w;
        if ((unsigned)n >= NN || (unsigned)e >= NE) continue;
        g_elist[atomicAdd(&g_posE[e], 1)] = n;
        g_nlist[atomicAdd(&g_posN[n], 1)] = e;
    }
}

// accumulate 8 fp16 channels (16 B) into 8 fp32 accumulators
__device__ __forceinline__ void acc_h8(float4& a0, float4& a1, const __half* p) {
    uint4 raw = *(const uint4*)p;
    float2 f0 = __half22float2(*(__half2*)&raw.x);
    float2 f1 = __half22float2(*(__half2*)&raw.y);
    float2 f2 = __half22float2(*(__half2*)&raw.z);
    float2 f3 = __half22float2(*(__half2*)&raw.w);
    a0.x += f0.x; a0.y += f0.y; a0.z += f1.x; a0.w += f1.y;
    a1.x += f2.x; a1.y += f2.y; a1.z += f3.x; a1.w += f3.y;
}

// ---------------- kernel 5: edge gather: ef[e] = Binv * sum xl[n] ------------
// HALF-warp per edge: 16 lanes x 16 B (8 channels); 8-way batched (MLP=8)
__global__ void k_gather_edge() {
    int warp = (blockIdx.x * blockDim.x + threadIdx.x) >> 5;
    int lane = threadIdx.x & 31;
    int sub  = lane & 15;                 // 8-channel chunk
    int e = warp * 2 + (lane >> 4);
    if (e >= NE) return;
    int s   = g_startE[e];
    int end = g_startE[e + 1];
    float4 a0 = make_float4(0.f, 0.f, 0.f, 0.f);
    float4 a1 = make_float4(0.f, 0.f, 0.f, 0.f);
    const __half* base = g_xlh + sub * 8;
    int j = s;
    for (; j + 8 <= end; j += 8) {
        int n[8];
#pragma unroll
        for (int q = 0; q < 8; q++) n[q] = g_elist[j + q];
        uint4 r[8];
#pragma unroll
        for (int q = 0; q < 8; q++)
            r[q] = *(const uint4*)(base + (size_t)n[q] * CH);
#pragma unroll
        for (int q = 0; q < 8; q++) {
            float2 f0 = __half22float2(*(__half2*)&r[q].x);
            float2 f1 = __half22float2(*(__half2*)&r[q].y);
            float2 f2 = __half22float2(*(__half2*)&r[q].z);
            float2 f3 = __half22float2(*(__half2*)&r[q].w);
            a0.x += f0.x; a0.y += f0.y; a0.z += f1.x; a0.w += f1.y;
            a1.x += f2.x; a1.y += f2.y; a1.z += f3.x; a1.w += f3.y;
        }
    }
    for (; j < end; j++)
        acc_h8(a0, a1, base + (size_t)g_elist[j] * CH);

    float binv = (end > s) ? (1.f / (float)(end - s)) : 0.f;
    uint4 raw;
    __half2 h;
    h = __floats2half2_rn(a0.x * binv, a0.y * binv); raw.x = *(unsigned*)&h;
    h = __floats2half2_rn(a0.z * binv, a0.w * binv); raw.y = *(unsigned*)&h;
    h = __floats2half2_rn(a1.x * binv, a1.y * binv); raw.z = *(unsigned*)&h;
    h = __floats2half2_rn(a1.z * binv, a1.w * binv); raw.w = *(unsigned*)&h;
    *(uint4*)(g_efh + (size_t)e * CH + sub * 8) = raw;
}

// ---------------- kernel 6: node gather + Dinv + bias ------------------------
// HALF-warp per node: 16 lanes x 16 B; 8-way batched (MLP=8)
__global__ void k_gather_node(float* __restrict__ out,
                              const float* __restrict__ bias) {
    int warp = (blockIdx.x * blockDim.x + threadIdx.x) >> 5;
    int lane = threadIdx.x & 31;
    int sub  = lane & 15;
    int n = warp * 2 + (lane >> 4);
    if (n >= NN) return;
    int s   = g_startN[n];
    int end = g_startN[n + 1];
    float4 a0 = make_float4(0.f, 0.f, 0.f, 0.f);
    float4 a1 = make_float4(0.f, 0.f, 0.f, 0.f);
    float dsum = 0.f;
    const __half* base = g_efh + sub * 8;
    int j = s;
    for (; j + 8 <= end; j += 8) {
        int e[8];
#pragma unroll
        for (int q = 0; q < 8; q++) e[q] = g_nlist[j + q];
        uint4 r[8];
#pragma unroll
        for (int q = 0; q < 8; q++)
            r[q] = *(const uint4*)(base + (size_t)e[q] * CH);
#pragma unroll
        for (int q = 0; q < 8; q++) dsum += __ldg(&g_w[e[q]]);
#pragma unroll
        for (int q = 0; q < 8; q++) {
            float2 f0 = __half22float2(*(__half2*)&r[q].x);
            float2 f1 = __half22float2(*(__half2*)&r[q].y);
            float2 f2 = __half22float2(*(__half2*)&r[q].z);
            float2 f3 = __half22float2(*(__half2*)&r[q].w);
            a0.x += f0.x; a0.y += f0.y; a0.z += f1.x; a0.w += f1.y;
            a1.x += f2.x; a1.y += f2.y; a1.z += f3.x; a1.w += f3.y;
        }
    }
    for (; j < end; j++) {
        int e = g_nlist[j];
        dsum += __ldg(&g_w[e]);
        acc_h8(a0, a1, base + (size_t)e * CH);
    }
    float dinv = (dsum > 0.f) ? (1.f / dsum) : 0.f;
    float4 b0 = *(const float4*)(bias + sub * 8);
    float4 b1 = *(const float4*)(bias + sub * 8 + 4);
    float* op = out + (size_t)n * CH + sub * 8;
    op[0] = fmaf(a0.x, dinv, b0.x);
    op[1] = fmaf(a0.y, dinv, b0.y);
    op[2] = fmaf(a0.z, dinv, b0.z);
    op[3] = fmaf(a0.w, dinv, b0.w);
    op[4] = fmaf(a1.x, dinv, b1.x);
    op[5] = fmaf(a1.y, dinv, b1.y);
    op[6] = fmaf(a1.z, dinv, b1.z);
    op[7] = fmaf(a1.w, dinv, b1.w);
}

// ---------------- launch: fork GEMM || CSR-build, join before gathers --------
extern "C" void kernel_launch(void* const* d_in, const int* in_sizes, int n_in,
                              void* d_out, int out_size) {
    const float* x      = (const float*)d_in[0];     // [50000,128] f32
    const int*   he     = (const int*)d_in[1];       // [2,800000] int32
    const float* attn_w = (const float*)d_in[2];     // [1,128]
    const float* attn_b = (const float*)d_in[3];     // [1]
    const float* lin_w  = (const float*)d_in[4];     // [128,128]
    const float* bias   = (const float*)d_in[5];     // [128]
    float*       out    = (float*)d_out;             // [50000,128]

    static cudaStream_t s2 = nullptr;
    static cudaEvent_t  evF = nullptr, evJ = nullptr;
    if (s2 == nullptr) {
        cudaStreamCreateWithFlags(&s2, cudaStreamNonBlocking);
        cudaEventCreateWithFlags(&evF, cudaEventDisableTiming);
        cudaEventCreateWithFlags(&evJ, cudaEventDisableTiming);
    }

    // fork: CSR-build chain on s2
    cudaEventRecord(evF, 0);
    cudaStreamWaitEvent(s2, evF, 0);

    k_zero<<<NBE, 256, 0, s2>>>();
    const int nq = (NNZV / 4 + 255) / 256;
    k_hist<<<nq, 256, 0, s2>>>(he);
    k_scanA<<<TOTB, 256, 0, s2>>>();
    k_scanC<<<TOTB, 256, 0, s2>>>();
    k_fill<<<nq, 256, 0, s2>>>(he);
    cudaEventRecord(evJ, s2);

    // GEMM on the main stream, concurrent with CSR build (1 wave: 148 blocks)
    const int smem = (128 * 132 + 128 * 34) * (int)sizeof(float);  // ~85 KB
    cudaFuncSetAttribute(k_gemm, cudaFuncAttributeMaxDynamicSharedMemorySize, smem);
    k_gemm<<<148, 128, smem>>>(x, lin_w, attn_w, attn_b);

    // join, then gathers
    cudaStreamWaitEvent(0, evJ, 0);
    const int gb = ((NE / 2) * 32 + 255) / 256;
    k_gather_edge<<<gb, 256>>>();
    k_gather_node<<<gb, 256>>>(out, bias);
}

// round 11
// speedup vs baseline: 1.3131x; 1.3131x over previous
#include <cuda_runtime.h>
#include <cuda_fp16.h>

#define NN 50000          // nodes
#define NE 50000          // hyperedges
#define CH 128            // channels
#define NNZV 800000       // nnz
#define NBE 196           // ceil(50000/256) blocks per scan domain
#define TOTB (2 * NBE)    // 392

// ---------------- scratch (device globals) -----------------------------------
__device__ float  g_w[NN];                        // sigmoid attention (per edge id)
__device__ __half g_xlh[(size_t)NN * CH];         // x @ lin_w^T  (fp16)
__device__ __half g_efh[(size_t)NE * CH];         // edge features (fp16, Binv-scaled)
__device__ int    g_cntE[NE];
__device__ int    g_cntN[NN];
__device__ int    g_posE[NE];                     // absolute fill cursors
__device__ int    g_posN[NN];
__device__ int    g_startE[NE + 1];
__device__ int    g_startN[NN + 1];
__device__ int    g_elist[NNZV];                  // node ids grouped by edge
__device__ int    g_nlist[NNZV];                  // edge ids grouped by node
__device__ int    g_blksum[TOTB];

// ---------------- kernel 0: zero counters ------------------------------------
__global__ void k_zero() {
    int i = blockIdx.x * blockDim.x + threadIdx.x;
    if (i < NE) g_cntE[i] = 0;
    if (i < NN) g_cntN[i] = 0;
}

// ---------------- kernel 1: xl = x @ lin_w^T (fp16 out), w = sigmoid(...) ---
__global__ void k_gemm(const float* __restrict__ x,
                       const float* __restrict__ lin_w,
                       const float* __restrict__ attn_w,
                       const float* __restrict__ attn_b) {
    extern __shared__ float sm[];
    float* s_lin = sm;                 // [k][c] stride 132
    float* s_x   = sm + 128 * 132;     // [k][r] stride 34 (transposed tile)

    const int tid = threadIdx.x;
    for (int idx = tid; idx < CH * CH; idx += 128) {
        int c = idx >> 7, k = idx & 127;
        s_lin[k * 132 + c] = lin_w[idx];          // transpose
    }

    const int cg = tid & 31;   // channels [4*cg, 4*cg+3]
    const int rg = tid >> 5;   // rows [8*rg, 8*rg+7] of the tile

    const int ntiles = (NN + 31) / 32;
    for (int tile = blockIdx.x; tile < ntiles; tile += gridDim.x) {
        const int row0 = tile * 32;
        __syncthreads();
        for (int idx = tid; idx < 32 * CH; idx += 128) {
            int r = idx >> 7, k = idx & 127;
            int gr = row0 + r;
            s_x[k * 34 + r] = (gr < NN) ? x[(size_t)gr * CH + k] : 0.f;
        }
        __syncthreads();

        unsigned long long acc[4][4];   // [row-pair][channel], f32x2 packed
#pragma unroll
        for (int p = 0; p < 4; p++)
#pragma unroll
            for (int c = 0; c < 4; c++) acc[p][c] = 0ull;

#pragma unroll 4
        for (int k = 0; k < CH; k++) {
            const float4 w4 = *(const float4*)(s_lin + k * 132 + cg * 4);
            unsigned long long bw[4];
            asm("mov.b64 %0, {%1, %1};" : "=l"(bw[0]) : "f"(w4.x));
            asm("mov.b64 %0, {%1, %1};" : "=l"(bw[1]) : "f"(w4.y));
            asm("mov.b64 %0, {%1, %1};" : "=l"(bw[2]) : "f"(w4.z));
            asm("mov.b64 %0, {%1, %1};" : "=l"(bw[3]) : "f"(w4.w));
            const unsigned long long* xp =
                (const unsigned long long*)(s_x + k * 34 + rg * 8);
#pragma unroll
            for (int p = 0; p < 4; p++) {
                unsigned long long a = xp[p];
#pragma unroll
                for (int c = 0; c < 4; c++)
                    asm("fma.rn.f32x2 %0, %1, %2, %3;"
                        : "=l"(acc[p][c]) : "l"(a), "l"(bw[c]), "l"(acc[p][c]));
            }
        }

#pragma unroll
        for (int p = 0; p < 4; p++) {
            float r0v[4], r1v[4];
#pragma unroll
            for (int c = 0; c < 4; c++)
                asm("mov.b64 {%0, %1}, %2;"
                    : "=f"(r0v[c]), "=f"(r1v[c]) : "l"(acc[p][c]));
            int r0 = row0 + rg * 8 + 2 * p;
            if (r0 < NN) {
                __half2 h0 = __floats2half2_rn(r0v[0], r0v[1]);
                __half2 h1 = __floats2half2_rn(r0v[2], r0v[3]);
                *(__half2*)(g_xlh + (size_t)r0 * CH + cg * 4)     = h0;
                *(__half2*)(g_xlh + (size_t)r0 * CH + cg * 4 + 2) = h1;
            }
            if (r0 + 1 < NN) {
                __half2 h0 = __floats2half2_rn(r1v[0], r1v[1]);
                __half2 h1 = __floats2half2_rn(r1v[2], r1v[3]);
                *(__half2*)(g_xlh + (size_t)(r0 + 1) * CH + cg * 4)     = h0;
                *(__half2*)(g_xlh + (size_t)(r0 + 1) * CH + cg * 4 + 2) = h1;
            }
        }

        if (tid < 32) {
            int gr = row0 + tid;
            if (gr < NN) {
                float z = 0.f;
#pragma unroll 4
                for (int k = 0; k < CH; k++)
                    z = fmaf(s_x[k * 34 + tid], attn_w[k], z);
                z += attn_b[0];
                g_w[gr] = 1.f / (1.f + __expf(-z));
            }
        }
    }
}

// ---------------- kernel 2: histogram (degrees), 4 nnz per thread ------------
__global__ void k_hist(const int* __restrict__ he) {
    int i = blockIdx.x * blockDim.x + threadIdx.x;   // over NNZV/4 quads
    if (i >= NNZV / 4) return;
    int4 n4 = ((const int4*)he)[i];
    int4 e4 = ((const int4*)(he + NNZV))[i];
    if ((unsigned)e4.x < NE) atomicAdd(&g_cntE[e4.x], 1);
    if ((unsigned)e4.y < NE) atomicAdd(&g_cntE[e4.y], 1);
    if ((unsigned)e4.z < NE) atomicAdd(&g_cntE[e4.z], 1);
    if ((unsigned)e4.w < NE) atomicAdd(&g_cntE[e4.w], 1);
    if ((unsigned)n4.x < NN) atomicAdd(&g_cntN[n4.x], 1);
    if ((unsigned)n4.y < NN) atomicAdd(&g_cntN[n4.y], 1);
    if ((unsigned)n4.z < NN) atomicAdd(&g_cntN[n4.z], 1);
    if ((unsigned)n4.w < NN) atomicAdd(&g_cntN[n4.w], 1);
}

// ---------------- scan phase A: per-block sums -------------------------------
__global__ void k_scanA() {
    const int bid = blockIdx.x;
    const bool isE = bid < NBE;
    const int lb   = isE ? bid : bid - NBE;
    const int base = lb * 256 + threadIdx.x;
    const int* cnt = isE ? g_cntE : g_cntN;
    const int len  = isE ? NE : NN;

    int v = (base < len) ? cnt[base] : 0;
#pragma unroll
    for (int off = 16; off > 0; off >>= 1)
        v += __shfl_down_sync(0xffffffffu, v, off);
    __shared__ int ws[8];
    if ((threadIdx.x & 31) == 0) ws[threadIdx.x >> 5] = v;
    __syncthreads();
    if (threadIdx.x == 0) {
        int s = 0;
#pragma unroll
        for (int w = 0; w < 8; w++) s += ws[w];
        g_blksum[bid] = s;
    }
}

// ---------------- scan phase C: block prefix + local scan + starts/cursors ---
__global__ void k_scanC() {
    const int bid = blockIdx.x;
    const bool isE = bid < NBE;
    const int lb   = isE ? bid : bid - NBE;
    const int base = lb * 256 + threadIdx.x;
    const int* cnt = isE ? g_cntE : g_cntN;
    int* strt = isE ? g_startE : g_startN;
    int* pos  = isE ? g_posE   : g_posN;
    const int len  = isE ? NE : NN;
    const int t = threadIdx.x;

    __shared__ int ws[8];
    __shared__ int s_off;
    int pre = (t < lb) ? g_blksum[(isE ? 0 : NBE) + t] : 0;
#pragma unroll
    for (int off = 16; off > 0; off >>= 1)
        pre += __shfl_down_sync(0xffffffffu, pre, off);
    if ((t & 31) == 0) ws[t >> 5] = pre;
    __syncthreads();
    if (t == 0) {
        int s = 0;
#pragma unroll
        for (int w = 0; w < 8; w++) s += ws[w];
        s_off = s;
    }
    __syncthreads();

    __shared__ int s[256];
    int c = (base < len) ? cnt[base] : 0;
    s[t] = c;
    __syncthreads();
#pragma unroll
    for (int off = 1; off < 256; off <<= 1) {
        int v = (t >= off) ? s[t - off] : 0;
        __syncthreads();
        s[t] += v;
        __syncthreads();
    }
    int excl = s[t] - c + s_off;
    if (base < len) { strt[base] = excl; pos[base] = excl; }
    if (base == len - 1) strt[len] = excl + c;
}

// ---------------- kernel 4: fill CSR lists, 4 nnz per thread -----------------
__global__ void k_fill(const int* __restrict__ he) {
    int i = blockIdx.x * blockDim.x + threadIdx.x;   // over NNZV/4 quads
    if (i >= NNZV / 4) return;
    int4 n4 = ((const int4*)he)[i];
    int4 e4 = ((const int4*)(he + NNZV))[i];
#pragma unroll
    for (int q = 0; q < 4; q++) {
        int n = (q == 0) ? n4.x : (q == 1) ? n4.y : (q == 2) ? n4.z : n4.w;
        int e = (q == 0) ? e4.x : (q == 1) ? e4.y : (q == 2) ? e4.z : e4.w;
        if ((unsigned)n >= NN || (unsigned)e >= NE) continue;
        g_elist[atomicAdd(&g_posE[e], 1)] = n;
        g_nlist[atomicAdd(&g_posN[n], 1)] = e;
    }
}

// accumulate 8 fp16 channels (16 B) into 8 fp32 accumulators
__device__ __forceinline__ void acc_h8(float4& a0, float4& a1, const __half* p) {
    uint4 raw = *(const uint4*)p;
    float2 f0 = __half22float2(*(__half2*)&raw.x);
    float2 f1 = __half22float2(*(__half2*)&raw.y);
    float2 f2 = __half22float2(*(__half2*)&raw.z);
    float2 f3 = __half22float2(*(__half2*)&raw.w);
    a0.x += f0.x; a0.y += f0.y; a0.z += f1.x; a0.w += f1.y;
    a1.x += f2.x; a1.y += f2.y; a1.z += f3.x; a1.w += f3.y;
}

// ---------------- kernel 5: edge gather: ef[e] = Binv * sum xl[n] ------------
// HALF-warp per edge: 16 lanes x 16 B (8 channels); 4-way batched (MLP=4)
__global__ void __launch_bounds__(256, 8) k_gather_edge() {
    int warp = (blockIdx.x * blockDim.x + threadIdx.x) >> 5;
    int lane = threadIdx.x & 31;
    int sub  = lane & 15;                 // 8-channel chunk
    int e = warp * 2 + (lane >> 4);
    if (e >= NE) return;
    int s   = g_startE[e];
    int end = g_startE[e + 1];
    float4 a0 = make_float4(0.f, 0.f, 0.f, 0.f);
    float4 a1 = make_float4(0.f, 0.f, 0.f, 0.f);
    const __half* base = g_xlh + sub * 8;
    int j = s;
    for (; j + 4 <= end; j += 4) {
        int n0 = g_elist[j],     n1 = g_elist[j + 1];
        int n2 = g_elist[j + 2], n3 = g_elist[j + 3];
        acc_h8(a0, a1, base + (size_t)n0 * CH);
        acc_h8(a0, a1, base + (size_t)n1 * CH);
        acc_h8(a0, a1, base + (size_t)n2 * CH);
        acc_h8(a0, a1, base + (size_t)n3 * CH);
    }
    for (; j < end; j++)
        acc_h8(a0, a1, base + (size_t)g_elist[j] * CH);

    float binv = (end > s) ? (1.f / (float)(end - s)) : 0.f;
    uint4 raw;
    __half2 h;
    h = __floats2half2_rn(a0.x * binv, a0.y * binv); raw.x = *(unsigned*)&h;
    h = __floats2half2_rn(a0.z * binv, a0.w * binv); raw.y = *(unsigned*)&h;
    h = __floats2half2_rn(a1.x * binv, a1.y * binv); raw.z = *(unsigned*)&h;
    h = __floats2half2_rn(a1.z * binv, a1.w * binv); raw.w = *(unsigned*)&h;
    *(uint4*)(g_efh + (size_t)e * CH + sub * 8) = raw;
}

// ---------------- kernel 6: node gather + Dinv + bias ------------------------
// HALF-warp per node: 16 lanes x 16 B; 4-way batched (MLP=4)
__global__ void __launch_bounds__(256, 8) k_gather_node(float* __restrict__ out,
                                                        const float* __restrict__ bias) {
    int warp = (blockIdx.x * blockDim.x + threadIdx.x) >> 5;
    int lane = threadIdx.x & 31;
    int sub  = lane & 15;
    int n = warp * 2 + (lane >> 4);
    if (n >= NN) return;
    int s   = g_startN[n];
    int end = g_startN[n + 1];
    float4 a0 = make_float4(0.f, 0.f, 0.f, 0.f);
    float4 a1 = make_float4(0.f, 0.f, 0.f, 0.f);
    float dsum = 0.f;
    const __half* base = g_efh + sub * 8;
    int j = s;
    for (; j + 4 <= end; j += 4) {
        int e0 = g_nlist[j],     e1 = g_nlist[j + 1];
        int e2 = g_nlist[j + 2], e3 = g_nlist[j + 3];
        dsum += __ldg(&g_w[e0]) + __ldg(&g_w[e1]) + __ldg(&g_w[e2]) + __ldg(&g_w[e3]);
        acc_h8(a0, a1, base + (size_t)e0 * CH);
        acc_h8(a0, a1, base + (size_t)e1 * CH);
        acc_h8(a0, a1, base + (size_t)e2 * CH);
        acc_h8(a0, a1, base + (size_t)e3 * CH);
    }
    for (; j < end; j++) {
        int e = g_nlist[j];
        dsum += __ldg(&g_w[e]);
        acc_h8(a0, a1, base + (size_t)e * CH);
    }
    float dinv = (dsum > 0.f) ? (1.f / dsum) : 0.f;
    float4 b0 = *(const float4*)(bias + sub * 8);
    float4 b1 = *(const float4*)(bias + sub * 8 + 4);
    float* op = out + (size_t)n * CH + sub * 8;
    op[0] = fmaf(a0.x, dinv, b0.x);
    op[1] = fmaf(a0.y, dinv, b0.y);
    op[2] = fmaf(a0.z, dinv, b0.z);
    op[3] = fmaf(a0.w, dinv, b0.w);
    op[4] = fmaf(a1.x, dinv, b1.x);
    op[5] = fmaf(a1.y, dinv, b1.y);
    op[6] = fmaf(a1.z, dinv, b1.z);
    op[7] = fmaf(a1.w, dinv, b1.w);
}

// ---------------- launch: fork GEMM || CSR-build, join before gathers --------
extern "C" void kernel_launch(void* const* d_in, const int* in_sizes, int n_in,
                              void* d_out, int out_size) {
    const float* x      = (const float*)d_in[0];     // [50000,128] f32
    const int*   he     = (const int*)d_in[1];       // [2,800000] int32
    const float* attn_w = (const float*)d_in[2];     // [1,128]
    const float* attn_b = (const float*)d_in[3];     // [1]
    const float* lin_w  = (const float*)d_in[4];     // [128,128]
    const float* bias   = (const float*)d_in[5];     // [128]
    float*       out    = (float*)d_out;             // [50000,128]

    static cudaStream_t s2 = nullptr;
    static cudaEvent_t  evF = nullptr, evJ = nullptr;
    if (s2 == nullptr) {
        cudaStreamCreateWithFlags(&s2, cudaStreamNonBlocking);
        cudaEventCreateWithFlags(&evF, cudaEventDisableTiming);
        cudaEventCreateWithFlags(&evJ, cudaEventDisableTiming);
    }

    // fork: CSR-build chain on s2
    cudaEventRecord(evF, 0);
    cudaStreamWaitEvent(s2, evF, 0);

    k_zero<<<NBE, 256, 0, s2>>>();
    const int nq = (NNZV / 4 + 255) / 256;
    k_hist<<<nq, 256, 0, s2>>>(he);
    k_scanA<<<TOTB, 256, 0, s2>>>();
    k_scanC<<<TOTB, 256, 0, s2>>>();
    k_fill<<<nq, 256, 0, s2>>>(he);
    cudaEventRecord(evJ, s2);

    // GEMM on the main stream, concurrent with CSR build (2 blocks/SM)
    const int smem = (128 * 132 + 128 * 34) * (int)sizeof(float);  // ~85 KB
    cudaFuncSetAttribute(k_gemm, cudaFuncAttributeMaxDynamicSharedMemorySize, smem);
    k_gemm<<<296, 128, smem>>>(x, lin_w, attn_w, attn_b);

    // join, then gathers
    cudaStreamWaitEvent(0, evJ, 0);
    const int gb = ((NE / 2) * 32 + 255) / 256;
    k_gather_edge<<<gb, 256>>>();
    k_gather_node<<<gb, 256>>>(out, bias);
}

// round 12
// speedup vs baseline: 1.3176x; 1.0034x over previous
#include <cuda_runtime.h>
#include <cuda_fp16.h>

#define NN 50000          // nodes
#define NE 50000          // hyperedges
#define CH 128            // channels
#define NNZV 800000       // nnz
#define NBE 196           // ceil(50000/256) blocks per scan domain
#define TOTB (2 * NBE)    // 392

// ---------------- scratch (device globals; zero-initialized at load) ---------
__device__ float  g_w[NN];                        // sigmoid attention (per edge id)
__device__ __half g_xlh[(size_t)NN * CH];         // x @ lin_w^T  (fp16)
__device__ __half g_efh[(size_t)NE * CH];         // edge features (fp16, Binv-scaled)
__device__ int    g_cntE[NE];                     // zeroed by k_scanC for next run
__device__ int    g_cntN[NN];
__device__ int    g_posE[NE];                     // absolute fill cursors
__device__ int    g_posN[NN];
__device__ int    g_startE[NE + 1];
__device__ int    g_startN[NN + 1];
__device__ int    g_elist[NNZV];                  // node ids grouped by edge
__device__ int    g_nlist[NNZV];                  // edge ids grouped by node
__device__ int    g_blksum[TOTB];

// ---------------- kernel 1: xl = x @ lin_w^T (fp16 out), w = sigmoid(...) ---
__global__ void k_gemm(const float* __restrict__ x,
                       const float* __restrict__ lin_w,
                       const float* __restrict__ attn_w,
                       const float* __restrict__ attn_b) {
    extern __shared__ float sm[];
    float* s_lin = sm;                 // [k][c] stride 132
    float* s_x   = sm + 128 * 132;     // [k][r] stride 34 (transposed tile)

    const int tid = threadIdx.x;
    for (int idx = tid; idx < CH * CH; idx += 128) {
        int c = idx >> 7, k = idx & 127;
        s_lin[k * 132 + c] = lin_w[idx];          // transpose
    }

    const int cg = tid & 31;   // channels [4*cg, 4*cg+3]
    const int rg = tid >> 5;   // rows [8*rg, 8*rg+7] of the tile

    const int ntiles = (NN + 31) / 32;
    for (int tile = blockIdx.x; tile < ntiles; tile += gridDim.x) {
        const int row0 = tile * 32;
        __syncthreads();
        for (int idx = tid; idx < 32 * CH; idx += 128) {
            int r = idx >> 7, k = idx & 127;
            int gr = row0 + r;
            s_x[k * 34 + r] = (gr < NN) ? x[(size_t)gr * CH + k] : 0.f;
        }
        __syncthreads();

        unsigned long long acc[4][4];   // [row-pair][channel], f32x2 packed
#pragma unroll
        for (int p = 0; p < 4; p++)
#pragma unroll
            for (int c = 0; c < 4; c++) acc[p][c] = 0ull;

#pragma unroll 4
        for (int k = 0; k < CH; k++) {
            const float4 w4 = *(const float4*)(s_lin + k * 132 + cg * 4);
            unsigned long long bw[4];
            asm("mov.b64 %0, {%1, %1};" : "=l"(bw[0]) : "f"(w4.x));
            asm("mov.b64 %0, {%1, %1};" : "=l"(bw[1]) : "f"(w4.y));
            asm("mov.b64 %0, {%1, %1};" : "=l"(bw[2]) : "f"(w4.z));
            asm("mov.b64 %0, {%1, %1};" : "=l"(bw[3]) : "f"(w4.w));
            const unsigned long long* xp =
                (const unsigned long long*)(s_x + k * 34 + rg * 8);
#pragma unroll
            for (int p = 0; p < 4; p++) {
                unsigned long long a = xp[p];
#pragma unroll
                for (int c = 0; c < 4; c++)
                    asm("fma.rn.f32x2 %0, %1, %2, %3;"
                        : "=l"(acc[p][c]) : "l"(a), "l"(bw[c]), "l"(acc[p][c]));
            }
        }

#pragma unroll
        for (int p = 0; p < 4; p++) {
            float r0v[4], r1v[4];
#pragma unroll
            for (int c = 0; c < 4; c++)
                asm("mov.b64 {%0, %1}, %2;"
                    : "=f"(r0v[c]), "=f"(r1v[c]) : "l"(acc[p][c]));
            int r0 = row0 + rg * 8 + 2 * p;
            if (r0 < NN) {
                __half2 h0 = __floats2half2_rn(r0v[0], r0v[1]);
                __half2 h1 = __floats2half2_rn(r0v[2], r0v[3]);
                *(__half2*)(g_xlh + (size_t)r0 * CH + cg * 4)     = h0;
                *(__half2*)(g_xlh + (size_t)r0 * CH + cg * 4 + 2) = h1;
            }
            if (r0 + 1 < NN) {
                __half2 h0 = __floats2half2_rn(r1v[0], r1v[1]);
                __half2 h1 = __floats2half2_rn(r1v[2], r1v[3]);
                *(__half2*)(g_xlh + (size_t)(r0 + 1) * CH + cg * 4)     = h0;
                *(__half2*)(g_xlh + (size_t)(r0 + 1) * CH + cg * 4 + 2) = h1;
            }
        }

        if (tid < 32) {
            int gr = row0 + tid;
            if (gr < NN) {
                float z = 0.f;
#pragma unroll 4
                for (int k = 0; k < CH; k++)
                    z = fmaf(s_x[k * 34 + tid], attn_w[k], z);
                z += attn_b[0];
                g_w[gr] = 1.f / (1.f + __expf(-z));
            }
        }
    }
}

// ---------------- kernel 2: histogram (degrees) ------------------------------
__global__ void k_hist(const int* __restrict__ he) {
    int i = blockIdx.x * blockDim.x + threadIdx.x;
    if (i >= NNZV) return;
    unsigned n = (unsigned)he[i];
    unsigned e = (unsigned)he[NNZV + i];
    if (e < NE) atomicAdd(&g_cntE[e], 1);
    if (n < NN) atomicAdd(&g_cntN[n], 1);
}

// ---------------- scan phase A: per-block sums -------------------------------
__global__ void k_scanA() {
    const int bid = blockIdx.x;
    const bool isE = bid < NBE;
    const int lb   = isE ? bid : bid - NBE;
    const int base = lb * 256 + threadIdx.x;
    const int* cnt = isE ? g_cntE : g_cntN;
    const int len  = isE ? NE : NN;

    int v = (base < len) ? cnt[base] : 0;
#pragma unroll
    for (int off = 16; off > 0; off >>= 1)
        v += __shfl_down_sync(0xffffffffu, v, off);
    __shared__ int ws[8];
    if ((threadIdx.x & 31) == 0) ws[threadIdx.x >> 5] = v;
    __syncthreads();
    if (threadIdx.x == 0) {
        int s = 0;
#pragma unroll
        for (int w = 0; w < 8; w++) s += ws[w];
        g_blksum[bid] = s;
    }
}

// ---------------- scan phase C: block prefix + local scan + starts/cursors ---
// Also resets cnt[] to zero for the next invocation (replay-safe).
__global__ void k_scanC() {
    const int bid = blockIdx.x;
    const bool isE = bid < NBE;
    const int lb   = isE ? bid : bid - NBE;
    const int base = lb * 256 + threadIdx.x;
    int* cnt  = isE ? g_cntE : g_cntN;
    int* strt = isE ? g_startE : g_startN;
    int* pos  = isE ? g_posE   : g_posN;
    const int len  = isE ? NE : NN;
    const int t = threadIdx.x;

    __shared__ int ws[8];
    __shared__ int s_off;
    int pre = (t < lb) ? g_blksum[(isE ? 0 : NBE) + t] : 0;
#pragma unroll
    for (int off = 16; off > 0; off >>= 1)
        pre += __shfl_down_sync(0xffffffffu, pre, off);
    if ((t & 31) == 0) ws[t >> 5] = pre;
    __syncthreads();
    if (t == 0) {
        int s = 0;
#pragma unroll
        for (int w = 0; w < 8; w++) s += ws[w];
        s_off = s;
    }
    __syncthreads();

    __shared__ int s[256];
    int c = 0;
    if (base < len) { c = cnt[base]; cnt[base] = 0; }   // read + self-clean
    s[t] = c;
    __syncthreads();
#pragma unroll
    for (int off = 1; off < 256; off <<= 1) {
        int v = (t >= off) ? s[t - off] : 0;
        __syncthreads();
        s[t] += v;
        __syncthreads();
    }
    int excl = s[t] - c + s_off;
    if (base < len) { strt[base] = excl; pos[base] = excl; }
    if (base == len - 1) strt[len] = excl + c;
}

// ---------------- kernel 4: fill CSR adjacency lists (absolute cursors) ------
__global__ void k_fill(const int* __restrict__ he) {
    int i = blockIdx.x * blockDim.x + threadIdx.x;
    if (i >= NNZV) return;
    unsigned n = (unsigned)he[i];
    unsigned e = (unsigned)he[NNZV + i];
    if (n >= NN || e >= NE) return;
    g_elist[atomicAdd(&g_posE[e], 1)] = (int)n;
    g_nlist[atomicAdd(&g_posN[n], 1)] = (int)e;
}

// accumulate 8 fp16 channels (16 B) into 8 fp32 accumulators
__device__ __forceinline__ void acc_h8(float4& a0, float4& a1, const __half* p) {
    uint4 raw = *(const uint4*)p;
    float2 f0 = __half22float2(*(__half2*)&raw.x);
    float2 f1 = __half22float2(*(__half2*)&raw.y);
    float2 f2 = __half22float2(*(__half2*)&raw.z);
    float2 f3 = __half22float2(*(__half2*)&raw.w);
    a0.x += f0.x; a0.y += f0.y; a0.z += f1.x; a0.w += f1.y;
    a1.x += f2.x; a1.y += f2.y; a1.z += f3.x; a1.w += f3.y;
}

// ---------------- kernel 5: edge gather: ef[e] = Binv * sum xl[n] ------------
// HALF-warp per edge; 4-way batched with index prefetch (software pipeline)
__global__ void k_gather_edge() {
    int warp = (blockIdx.x * blockDim.x + threadIdx.x) >> 5;
    int lane = threadIdx.x & 31;
    int sub  = lane & 15;                 // 8-channel chunk
    int e = warp * 2 + (lane >> 4);
    if (e >= NE) return;
    int s   = g_startE[e];
    int end = g_startE[e + 1];
    float4 a0 = make_float4(0.f, 0.f, 0.f, 0.f);
    float4 a1 = make_float4(0.f, 0.f, 0.f, 0.f);
    const __half* base = g_xlh + sub * 8;

    int j = s;
    if (j + 4 <= end) {
        int n0 = g_elist[j], n1 = g_elist[j + 1];
        int n2 = g_elist[j + 2], n3 = g_elist[j + 3];
        j += 4;
        for (; j + 4 <= end; j += 4) {
            int m0 = g_elist[j],     m1 = g_elist[j + 1];   // prefetch next
            int m2 = g_elist[j + 2], m3 = g_elist[j + 3];
            acc_h8(a0, a1, base + (size_t)n0 * CH);
            acc_h8(a0, a1, base + (size_t)n1 * CH);
            acc_h8(a0, a1, base + (size_t)n2 * CH);
            acc_h8(a0, a1, base + (size_t)n3 * CH);
            n0 = m0; n1 = m1; n2 = m2; n3 = m3;
        }
        acc_h8(a0, a1, base + (size_t)n0 * CH);
        acc_h8(a0, a1, base + (size_t)n1 * CH);
        acc_h8(a0, a1, base + (size_t)n2 * CH);
        acc_h8(a0, a1, base + (size_t)n3 * CH);
    }
    for (; j < end; j++)
        acc_h8(a0, a1, base + (size_t)g_elist[j] * CH);

    float binv = (end > s) ? (1.f / (float)(end - s)) : 0.f;
    uint4 raw;
    __half2 h;
    h = __floats2half2_rn(a0.x * binv, a0.y * binv); raw.x = *(unsigned*)&h;
    h = __floats2half2_rn(a0.z * binv, a0.w * binv); raw.y = *(unsigned*)&h;
    h = __floats2half2_rn(a1.x * binv, a1.y * binv); raw.z = *(unsigned*)&h;
    h = __floats2half2_rn(a1.z * binv, a1.w * binv); raw.w = *(unsigned*)&h;
    *(uint4*)(g_efh + (size_t)e * CH + sub * 8) = raw;
}

// ---------------- kernel 6: node gather + Dinv + bias ------------------------
// HALF-warp per node; 4-way batched with index prefetch
__global__ void k_gather_node(float* __restrict__ out,
                              const float* __restrict__ bias) {
    int warp = (blockIdx.x * blockDim.x + threadIdx.x) >> 5;
    int lane = threadIdx.x & 31;
    int sub  = lane & 15;
    int n = warp * 2 + (lane >> 4);
    if (n >= NN) return;
    int s   = g_startN[n];
    int end = g_startN[n + 1];
    float4 a0 = make_float4(0.f, 0.f, 0.f, 0.f);
    float4 a1 = make_float4(0.f, 0.f, 0.f, 0.f);
    float dsum = 0.f;
    const __half* base = g_efh + sub * 8;

    int j = s;
    if (j + 4 <= end) {
        int e0 = g_nlist[j], e1 = g_nlist[j + 1];
        int e2 = g_nlist[j + 2], e3 = g_nlist[j + 3];
        j += 4;
        for (; j + 4 <= end; j += 4) {
            int f0 = g_nlist[j],     f1 = g_nlist[j + 1];   // prefetch next
            int f2 = g_nlist[j + 2], f3 = g_nlist[j + 3];
            dsum += __ldg(&g_w[e0]) + __ldg(&g_w[e1]) + __ldg(&g_w[e2]) + __ldg(&g_w[e3]);
            acc_h8(a0, a1, base + (size_t)e0 * CH);
            acc_h8(a0, a1, base + (size_t)e1 * CH);
            acc_h8(a0, a1, base + (size_t)e2 * CH);
            acc_h8(a0, a1, base + (size_t)e3 * CH);
            e0 = f0; e1 = f1; e2 = f2; e3 = f3;
        }
        dsum += __ldg(&g_w[e0]) + __ldg(&g_w[e1]) + __ldg(&g_w[e2]) + __ldg(&g_w[e3]);
        acc_h8(a0, a1, base + (size_t)e0 * CH);
        acc_h8(a0, a1, base + (size_t)e1 * CH);
        acc_h8(a0, a1, base + (size_t)e2 * CH);
        acc_h8(a0, a1, base + (size_t)e3 * CH);
    }
    for (; j < end; j++) {
        int e = g_nlist[j];
        dsum += __ldg(&g_w[e]);
        acc_h8(a0, a1, base + (size_t)e * CH);
    }
    float dinv = (dsum > 0.f) ? (1.f / dsum) : 0.f;
    float4 b0 = *(const float4*)(bias + sub * 8);
    float4 b1 = *(const float4*)(bias + sub * 8 + 4);
    float* op = out + (size_t)n * CH + sub * 8;
    op[0] = fmaf(a0.x, dinv, b0.x);
    op[1] = fmaf(a0.y, dinv, b0.y);
    op[2] = fmaf(a0.z, dinv, b0.z);
    op[3] = fmaf(a0.w, dinv, b0.w);
    op[4] = fmaf(a1.x, dinv, b1.x);
    op[5] = fmaf(a1.y, dinv, b1.y);
    op[6] = fmaf(a1.z, dinv, b1.z);
    op[7] = fmaf(a1.w, dinv, b1.w);
}

// ---------------- launch: fork GEMM || CSR-build, join before gathers --------
extern "C" void kernel_launch(void* const* d_in, const int* in_sizes, int n_in,
                              void* d_out, int out_size) {
    const float* x      = (const float*)d_in[0];     // [50000,128] f32
    const int*   he     = (const int*)d_in[1];       // [2,800000] int32
    const float* attn_w = (const float*)d_in[2];     // [1,128]
    const float* attn_b = (const float*)d_in[3];     // [1]
    const float* lin_w  = (const float*)d_in[4];     // [128,128]
    const float* bias   = (const float*)d_in[5];     // [128]
    float*       out    = (float*)d_out;             // [50000,128]

    static cudaStream_t s2 = nullptr;
    static cudaEvent_t  evF = nullptr, evJ = nullptr;
    if (s2 == nullptr) {
        cudaStreamCreateWithFlags(&s2, cudaStreamNonBlocking);
        cudaEventCreateWithFlags(&evF, cudaEventDisableTiming);
        cudaEventCreateWithFlags(&evJ, cudaEventDisableTiming);
    }

    // fork: CSR-build chain on s2 (counters are zero on entry; scanC re-zeroes)
    cudaEventRecord(evF, 0);
    cudaStreamWaitEvent(s2, evF, 0);

    const int nb = (NNZV + 255) / 256;
    k_hist<<<nb, 256, 0, s2>>>(he);
    k_scanA<<<TOTB, 256, 0, s2>>>();
    k_scanC<<<TOTB, 256, 0, s2>>>();
    k_fill<<<nb, 256, 0, s2>>>(he);
    cudaEventRecord(evJ, s2);

    // GEMM on the main stream, concurrent with CSR build (2 blocks/SM)
    const int smem = (128 * 132 + 128 * 34) * (int)sizeof(float);  // ~85 KB
    cudaFuncSetAttribute(k_gemm, cudaFuncAttributeMaxDynamicSharedMemorySize, smem);
    k_gemm<<<296, 128, smem>>>(x, lin_w, attn_w, attn_b);

    // join, then gathers
    cudaStreamWaitEvent(0, evJ, 0);
    const int gb = ((NE / 2) * 32 + 255) / 256;
    k_gather_edge<<<gb, 256>>>();
    k_gather_node<<<gb, 256>>>(out, bias);
}